// round 1
// baseline (speedup 1.0000x reference)
#include <cuda_runtime.h>
#include <math.h>

#define Bsz    4096
#define Dh     256
#define NROW   8192          // 2 * Bsz
#define TEMP_INV 10.0f       // 1 / 0.1
#define BM     128
#define BN     256
#define BK     32
#define NCHUNK 8
#define JT_PER_CHUNK 4       // (NROW / NCHUNK) / BN
#define AS_LD  260           // 256 + 4 pad (float4-aligned)
#define BS_LD  260           // 256 + 4 pad
#define SMEM_BYTES ((BM*AS_LD + BK*BS_LD) * 4)   // 166400 B

// ---------------- device scratch (no allocations allowed) ----------------
__device__ float g_hsn [Bsz * Dh];
__device__ float g_ht0n[Bsz * Dh];
__device__ float g_ht1n[Bsz * Dh];
__device__ float g_self[3 * Bsz];
__device__ int   g_hist[256];
__device__ float g_Zpart[2 * NCHUNK * NROW];
__device__ float g_Spart[2 * NCHUNK * NROW];

// ---------------- packed f32x2 helpers (sm_100+) ----------------
__device__ __forceinline__ unsigned long long pk2(float a, float b) {
    unsigned long long r;
    asm("mov.b64 %0, {%1, %2};" : "=l"(r) : "f"(a), "f"(b));
    return r;
}
__device__ __forceinline__ void upk2(unsigned long long v, float& a, float& b) {
    asm("mov.b64 {%0, %1}, %2;" : "=f"(a), "=f"(b) : "l"(v));
}
__device__ __forceinline__ void fma2(unsigned long long& d,
                                     unsigned long long a,
                                     unsigned long long b) {
    asm("fma.rn.f32x2 %0, %1, %2, %0;" : "+l"(d) : "l"(a), "l"(b));
}

// ---------------- 1) L2-normalize rows, record self-dot ----------------
__global__ void normalize_k(const float* __restrict__ hs,
                            const float* __restrict__ ht0,
                            const float* __restrict__ ht1) {
    int which = blockIdx.x / Bsz;
    int row   = blockIdx.x - which * Bsz;
    const float* src = (which == 0) ? hs : (which == 1) ? ht0 : ht1;
    float*       dst = (which == 0) ? g_hsn : (which == 1) ? g_ht0n : g_ht1n;

    int t = threadIdx.x;                 // 256 threads, 1 elem each
    float x = src[row * Dh + t];
    float v = x * x;
    #pragma unroll
    for (int o = 16; o; o >>= 1) v += __shfl_xor_sync(0xffffffffu, v, o);
    __shared__ float ws[8];
    if ((t & 31) == 0) ws[t >> 5] = v;
    __syncthreads();
    float ss = 0.f;
    #pragma unroll
    for (int i = 0; i < 8; ++i) ss += ws[i];

    float n   = fmaxf(sqrtf(ss), 1e-12f);   // matches F.normalize
    float inv = 1.0f / n;
    dst[row * Dh + t] = x * inv;
    if (t == 0) g_self[which * Bsz + row] = ss * inv * inv;
}

// ---------------- 2) label histogram (int atomics: deterministic) ----------
__global__ void hist_k(const int* __restrict__ labels) {
    __shared__ int h[256];
    int t = threadIdx.x;
    h[t] = 0;
    __syncthreads();
    for (int i = t; i < Bsz; i += 256) atomicAdd(&h[labels[i] & 255], 1);
    __syncthreads();
    g_hist[t] = h[t];
}

// ---------------- 3) fused sim-GEMM + exp/mask row reduction ----------------
// grid = (NROW/BM, NCHUNK, 2 teachers), block = 256 (ty 16 x tx 16)
// Each thread: 8 rows x 16 cols micro-tile via packed f32x2 FMAs.
extern __shared__ float smem[];

__global__ void __launch_bounds__(256, 1)
contrast_gemm(const int* __restrict__ labels) {
    float* As  = smem;                    // [BM][AS_LD]  row-major, full K=256
    float* Bsh = smem + BM * AS_LD;       // [BK][BS_LD]  k-major (transposed)

    const int teach = blockIdx.z;
    const float* htn = teach ? g_ht1n : g_ht0n;
    const int i0    = blockIdx.x * BM;
    const int chunk = blockIdx.y;

    const float* Abase = (i0 < Bsz) ? (g_hsn + i0 * Dh)
                                    : (htn + (i0 - Bsz) * Dh);

    const int tid = threadIdx.x;
    const int tx  = tid & 15;             // col group
    const int ty  = tid >> 4;             // row group
    const int m0  = ty * 8;
    const int n0  = tx * 16;

    // Load full A strip (128 x 256 fp32) once — stays resident all block.
    #pragma unroll
    for (int it = 0; it < 32; ++it) {
        int f = tid + it * 256;
        int r = f >> 6, q = f & 63;
        float4 v = *reinterpret_cast<const float4*>(Abase + r * Dh + 4 * q);
        *reinterpret_cast<float4*>(As + r * AS_LD + 4 * q) = v;
    }

    int labr[8];
    #pragma unroll
    for (int r = 0; r < 8; ++r)
        labr[r] = __ldg(&labels[(i0 + m0 + r) & (Bsz - 1)]);

    float zk[8], sk[8];
    #pragma unroll
    for (int r = 0; r < 8; ++r) { zk[r] = 0.f; sk[r] = 0.f; }

    __syncthreads();

    for (int jt = 0; jt < JT_PER_CHUNK; ++jt) {
        const int j0 = chunk * (NROW / NCHUNK) + jt * BN;
        const float* Ybase = (j0 < Bsz) ? (g_hsn + j0 * Dh)
                                        : (htn + (j0 - Bsz) * Dh);
        int labc[16];
        #pragma unroll
        for (int c = 0; c < 16; ++c)
            labc[c] = __ldg(&labels[(j0 + n0 + c) & (Bsz - 1)]);

        unsigned long long acc[64];
        #pragma unroll
        for (int i = 0; i < 64; ++i) acc[i] = 0ull;

        for (int kk = 0; kk < Dh; kk += BK) {
            __syncthreads();
            // Load B tile transposed: Bsh[k][jlocal]
            #pragma unroll
            for (int it = 0; it < 8; ++it) {
                int f = tid + it * 256;
                int j = f >> 3, q = f & 7;
                float4 v = *reinterpret_cast<const float4*>(
                    Ybase + j * Dh + kk + 4 * q);
                Bsh[(4 * q + 0) * BS_LD + j] = v.x;
                Bsh[(4 * q + 1) * BS_LD + j] = v.y;
                Bsh[(4 * q + 2) * BS_LD + j] = v.z;
                Bsh[(4 * q + 3) * BS_LD + j] = v.w;
            }
            __syncthreads();

            #pragma unroll 4
            for (int k = 0; k < BK; ++k) {
                float af[8];
                #pragma unroll
                for (int j = 0; j < 8; ++j)
                    af[j] = As[(m0 + j) * AS_LD + kk + k];
                unsigned long long ap[4];
                #pragma unroll
                for (int p = 0; p < 4; ++p) ap[p] = pk2(af[2*p], af[2*p+1]);

                const float4* bp =
                    reinterpret_cast<const float4*>(Bsh + k * BS_LD + n0);
                float4 b4[4];
                #pragma unroll
                for (int q = 0; q < 4; ++q) b4[q] = bp[q];
                const float* bf = reinterpret_cast<const float*>(b4);

                #pragma unroll
                for (int c = 0; c < 16; ++c) {
                    unsigned long long bd = pk2(bf[c], bf[c]);
                    #pragma unroll
                    for (int p = 0; p < 4; ++p) fma2(acc[c*4 + p], ap[p], bd);
                }
            }
        }

        // Epilogue: logits -> exp & masked sums (registers only)
        #pragma unroll
        for (int c = 0; c < 16; ++c) {
            #pragma unroll
            for (int p = 0; p < 4; ++p) {
                float lo, hi;
                upk2(acc[c*4 + p], lo, hi);
                float s0 = lo * TEMP_INV, s1 = hi * TEMP_INV;
                zk[2*p]     += __expf(s0);
                zk[2*p + 1] += __expf(s1);
                if (labr[2*p]     == labc[c]) sk[2*p]     += s0;
                if (labr[2*p + 1] == labc[c]) sk[2*p + 1] += s1;
            }
        }
    }

    // Reduce over the 16 tx lanes (fixed order => deterministic)
    #pragma unroll
    for (int o = 1; o < 16; o <<= 1) {
        #pragma unroll
        for (int r = 0; r < 8; ++r) {
            zk[r] += __shfl_xor_sync(0xffffffffu, zk[r], o);
            sk[r] += __shfl_xor_sync(0xffffffffu, sk[r], o);
        }
    }
    if (tx == 0) {
        int base = (teach * NCHUNK + chunk) * NROW + i0 + m0;
        #pragma unroll
        for (int r = 0; r < 8; ++r) {
            g_Zpart[base + r] = zk[r];
            g_Spart[base + r] = sk[r];
        }
    }
}

// ---------------- 4) finalize: per-row loss + deterministic mean ----------
__global__ void finalize_k(const int* __restrict__ labels,
                           float* __restrict__ out) {
    int tid = threadIdx.x;                // 1024 threads
    double acc = 0.0;
    for (int g = tid; g < 2 * NROW; g += 1024) {
        int t = g >> 13;                  // teacher
        int i = g & (NROW - 1);
        float Z = 0.f, S = 0.f;
        int base = t * NCHUNK * NROW + i;
        #pragma unroll
        for (int c = 0; c < NCHUNK; ++c) {
            Z += g_Zpart[base + c * NROW];
            S += g_Spart[base + c * NROW];
        }
        float self = (i < Bsz) ? g_self[i]
                               : g_self[(t ? 2 : 1) * Bsz + (i - Bsz)];
        float sd = self * TEMP_INV;       // diagonal logit (~10)
        Z -= __expf(sd);                  // remove diagonal from Z
        S -= sd;                          // remove diagonal from masked sum
        int M = 2 * g_hist[labels[i & (Bsz - 1)] & 255] - 1;
        float p = logf(Z) - S / (float)M;
        acc += (double)p;
    }
    #pragma unroll
    for (int o = 16; o; o >>= 1) acc += __shfl_xor_sync(0xffffffffu, acc, o);
    __shared__ double ws[32];
    if ((tid & 31) == 0) ws[tid >> 5] = acc;
    __syncthreads();
    if (tid == 0) {
        double s = 0.0;
        #pragma unroll
        for (int i = 0; i < 32; ++i) s += ws[i];
        out[0] = (float)(s / (double)(2 * NROW));  // (mean0+mean1)/2
    }
}

// ---------------- launch ----------------
extern "C" void kernel_launch(void* const* d_in, const int* in_sizes, int n_in,
                              void* d_out, int out_size) {
    const float* hs     = (const float*)d_in[0];
    const float* ht0    = (const float*)d_in[1];
    const float* ht1    = (const float*)d_in[2];
    const int*   labels = (const int*)d_in[3];
    float*       out    = (float*)d_out;
    (void)in_sizes; (void)n_in; (void)out_size;

    normalize_k<<<3 * Bsz, 256>>>(hs, ht0, ht1);
    hist_k<<<1, 256>>>(labels);

    cudaFuncSetAttribute(contrast_gemm,
                         cudaFuncAttributeMaxDynamicSharedMemorySize,
                         SMEM_BYTES);
    dim3 grid(NROW / BM, NCHUNK, 2);
    contrast_gemm<<<grid, 256, SMEM_BYTES>>>(labels);

    finalize_k<<<1, 1024>>>(labels, out);
}

// round 3
// speedup vs baseline: 8.4922x; 8.4922x over previous
#include <cuda_runtime.h>
#include <cuda_bf16.h>
#include <math.h>
#include <stdint.h>

#define Bsz    4096
#define Dh     256
#define NROW   8192
#define TEMP_INV 10.0f
#define BM     128
#define BN     128
#define BK     32
#define NK     8              // 256 / 32
#define NJT    64             // 8192 / BN
#define ROWB   80             // smem row stride bytes (32 bf16 = 64B + 16B pad)
#define STAGE_B (2 * BM * ROWB)          // A tile + B tile = 20480 B
#define SM_STAGES (3 * STAGE_B)          // 61440
#define SM_CLAB   SM_STAGES              // 128 ints = 512 B
#define SM_ZRED   (SM_CLAB + 512)        // 128*2 floats = 1024 B
#define SM_SRED   (SM_ZRED + 1024)
#define SM_TOTAL  (SM_SRED + 1024)       // 64000

// ---------------- device scratch ----------------
__device__ __nv_bfloat16 g_hi[3 * Bsz * Dh];
__device__ float g_self[3 * Bsz];
__device__ int   g_hist[256];
__device__ float g_Zpart[2 * NJT * NROW];
__device__ float g_Spart[2 * NJT * NROW];
__device__ float g_rowloss[2 * NROW];

// ---------------- PTX helpers (family-generic, sm_80-era) ----------------
__device__ __forceinline__ uint32_t smem_u32(const void* p) {
    uint32_t a;
    asm("{ .reg .u64 t; cvta.to.shared.u64 t, %1; cvt.u32.u64 %0, t; }" : "=r"(a) : "l"(p));
    return a;
}
__device__ __forceinline__ void cp16(uint32_t dst, const void* src) {
    asm volatile("cp.async.cg.shared.global [%0], [%1], 16;" :: "r"(dst), "l"(src));
}
__device__ __forceinline__ void cp_commit() {
    asm volatile("cp.async.commit_group;");
}
__device__ __forceinline__ void cp_wait1() {
    asm volatile("cp.async.wait_group 1;");
}
__device__ __forceinline__ void ldm4(uint32_t& r0, uint32_t& r1, uint32_t& r2,
                                     uint32_t& r3, uint32_t addr) {
    asm volatile("ldmatrix.sync.aligned.m8n8.x4.shared.b16 {%0,%1,%2,%3}, [%4];"
                 : "=r"(r0), "=r"(r1), "=r"(r2), "=r"(r3) : "r"(addr));
}
__device__ __forceinline__ void mma16816(float* c, const uint32_t* a,
                                         uint32_t b0, uint32_t b1) {
    asm volatile("mma.sync.aligned.m16n8k16.row.col.f32.bf16.bf16.f32 "
                 "{%0,%1,%2,%3}, {%4,%5,%6,%7}, {%8,%9}, {%0,%1,%2,%3};"
                 : "+f"(c[0]), "+f"(c[1]), "+f"(c[2]), "+f"(c[3])
                 : "r"(a[0]), "r"(a[1]), "r"(a[2]), "r"(a[3]), "r"(b0), "r"(b1));
}

// ---------------- 1) normalize + bf16 round + consistent self-dot ----------
__global__ void prep_k(const float* __restrict__ hs, const float* __restrict__ t0,
                       const float* __restrict__ t1) {
    int which = blockIdx.x >> 12;
    int row   = blockIdx.x & (Bsz - 1);
    const float* src = (which == 0) ? hs : (which == 1) ? t0 : t1;
    int t = threadIdx.x;
    float x = src[row * Dh + t];
    float v = x * x;
    #pragma unroll
    for (int o = 16; o; o >>= 1) v += __shfl_xor_sync(0xffffffffu, v, o);
    __shared__ float ws[8];
    if ((t & 31) == 0) ws[t >> 5] = v;
    __syncthreads();
    float ss = ws[0] + ws[1] + ws[2] + ws[3] + ws[4] + ws[5] + ws[6] + ws[7];

    float inv = 1.0f / fmaxf(sqrtf(ss), 1e-12f);
    __nv_bfloat16 h = __float2bfloat16(x * inv);
    float hf = __bfloat162float(h);
    g_hi[(which * Bsz + row) * Dh + t] = h;

    // diagonal sim exactly as the MMA sees it: sum(hf^2)
    float sv = hf * hf;
    #pragma unroll
    for (int o = 16; o; o >>= 1) sv += __shfl_xor_sync(0xffffffffu, sv, o);
    __syncthreads();
    if ((t & 31) == 0) ws[t >> 5] = sv;
    __syncthreads();
    if (t == 0)
        g_self[which * Bsz + row] =
            ws[0] + ws[1] + ws[2] + ws[3] + ws[4] + ws[5] + ws[6] + ws[7];
}

// ---------------- 2) label histogram ----------------
__global__ void hist_k(const int* __restrict__ labels) {
    __shared__ int h[256];
    int t = threadIdx.x;
    h[t] = 0;
    __syncthreads();
    for (int i = t; i < Bsz; i += 256) atomicAdd(&h[labels[i] & 255], 1);
    __syncthreads();
    g_hist[t] = h[t];
}

// ---------------- 3) bf16 mma.sync sim-GEMM + exp/mask epilogue ----------
extern __shared__ char smem[];

__global__ void __launch_bounds__(256, 2)
contrast_gemm(const int* __restrict__ labels) {
    const int tid = threadIdx.x;
    const int wid = tid >> 5, lid = tid & 31;
    const int teach = blockIdx.z;
    const int i0 = blockIdx.x * BM;
    const int j0 = blockIdx.y * BN;

    const uint32_t sb = smem_u32(smem);

    const __nv_bfloat16* Ap = (i0 < Bsz)
        ? g_hi + i0 * Dh
        : g_hi + ((1 + teach) * Bsz + (i0 - Bsz)) * Dh;
    const __nv_bfloat16* Bp = (j0 < Bsz)
        ? g_hi + j0 * Dh
        : g_hi + ((1 + teach) * Bsz + (j0 - Bsz)) * Dh;

    // column labels LUT
    if (tid < BN)
        *reinterpret_cast<int*>(smem + SM_CLAB + tid * 4) =
            labels[(j0 + tid) & (Bsz - 1)];

    // copy assignment: thread -> rows (tid>>2, tid>>2 + 64), chunk tid&3
    const int cr = tid >> 2, cc = tid & 3;

    auto load_tile = [&](int kk, int stage) {
        uint32_t dst = sb + stage * STAGE_B;
        const __nv_bfloat16* ga = Ap + cr * Dh + kk + cc * 8;
        const __nv_bfloat16* gb = Bp + cr * Dh + kk + cc * 8;
        cp16(dst + cr * ROWB + cc * 16,                 ga);
        cp16(dst + (cr + 64) * ROWB + cc * 16,          ga + 64 * Dh);
        cp16(dst + BM * ROWB + cr * ROWB + cc * 16,      gb);
        cp16(dst + BM * ROWB + (cr + 64) * ROWB + cc * 16, gb + 64 * Dh);
    };

    load_tile(0, 0);
    cp_commit();
    load_tile(BK, 1);
    cp_commit();

    // warp layout: wr = wid&3 (M, 32 rows), wc = wid>>2 (N, 64 cols)
    const int wr = wid & 3, wc = wid >> 2;
    const int lrow = lid & 15;
    const int koff = (lid & 16) ? 16 : 0;

    float c[2][8][4];
    #pragma unroll
    for (int mi = 0; mi < 2; ++mi)
        #pragma unroll
        for (int ni = 0; ni < 8; ++ni)
            #pragma unroll
            for (int e = 0; e < 4; ++e) c[mi][ni][e] = 0.f;

    for (int k = 0; k < NK; ++k) {
        cp_wait1();
        __syncthreads();
        if (k + 2 < NK) load_tile((k + 2) * BK, (k + 2) % 3);
        cp_commit();

        uint32_t sA = sb + (k % 3) * STAGE_B;
        uint32_t sB = sA + BM * ROWB;

        #pragma unroll
        for (int ks = 0; ks < 2; ++ks) {
            uint32_t a[2][4], b[4][4];
            #pragma unroll
            for (int mi = 0; mi < 2; ++mi)
                ldm4(a[mi][0], a[mi][1], a[mi][2], a[mi][3],
                     sA + (32 * wr + 16 * mi + lrow) * ROWB + ks * 32 + koff);
            #pragma unroll
            for (int nj = 0; nj < 4; ++nj)
                ldm4(b[nj][0], b[nj][1], b[nj][2], b[nj][3],
                     sB + (64 * wc + 16 * nj + lrow) * ROWB + ks * 32 + koff);
            #pragma unroll
            for (int mi = 0; mi < 2; ++mi)
                #pragma unroll
                for (int ni = 0; ni < 8; ++ni) {
                    int nj = ni >> 1, h = ni & 1;
                    mma16816(c[mi][ni], a[mi], b[nj][h], b[nj][2 + h]);
                }
        }
        __syncthreads();
    }

    // ---- epilogue: exp + masked sums, all in registers ----
    const int* clab = reinterpret_cast<const int*>(smem + SM_CLAB);
    float* s_z = reinterpret_cast<float*>(smem + SM_ZRED);
    float* s_s = reinterpret_cast<float*>(smem + SM_SRED);

    int rlab[4];
    #pragma unroll
    for (int q = 0; q < 4; ++q)
        rlab[q] = labels[(i0 + 32 * wr + (lid >> 2) + 8 * q) & (Bsz - 1)];

    float zk[4], sk[4];
    #pragma unroll
    for (int q = 0; q < 4; ++q) { zk[q] = 0.f; sk[q] = 0.f; }

    #pragma unroll
    for (int mi = 0; mi < 2; ++mi)
        #pragma unroll
        for (int ni = 0; ni < 8; ++ni)
            #pragma unroll
            for (int e = 0; e < 4; ++e) {
                int q = mi * 2 + (e >> 1);
                int col = 64 * wc + 8 * ni + (lid & 3) * 2 + (e & 1);
                float lg = c[mi][ni][e] * TEMP_INV;
                zk[q] += __expf(lg);
                if (clab[col] == rlab[q]) sk[q] += lg;
            }

    #pragma unroll
    for (int q = 0; q < 4; ++q) {
        #pragma unroll
        for (int o = 1; o < 4; o <<= 1) {
            zk[q] += __shfl_xor_sync(0xffffffffu, zk[q], o);
            sk[q] += __shfl_xor_sync(0xffffffffu, sk[q], o);
        }
    }
    if ((lid & 3) == 0) {
        #pragma unroll
        for (int q = 0; q < 4; ++q) {
            int row = 32 * wr + (lid >> 2) + 8 * q;
            s_z[row * 2 + wc] = zk[q];
            s_s[row * 2 + wc] = sk[q];
        }
    }
    __syncthreads();
    if (tid < BM) {
        float Z = s_z[tid * 2] + s_z[tid * 2 + 1];
        float S = s_s[tid * 2] + s_s[tid * 2 + 1];
        int idx = (teach * NJT + blockIdx.y) * NROW + i0 + tid;
        g_Zpart[idx] = Z;
        g_Spart[idx] = S;
    }
}

// ---------------- 4a) per-row loss ----------------
__global__ void finalize1(const int* __restrict__ labels) {
    int g = blockIdx.x * 1024 + threadIdx.x;     // 0..16383
    int t = g >> 13;
    int i = g & (NROW - 1);
    float Z = 0.f, S = 0.f;
    #pragma unroll
    for (int c = 0; c < NJT; ++c) {
        Z += g_Zpart[(t * NJT + c) * NROW + i];
        S += g_Spart[(t * NJT + c) * NROW + i];
    }
    float self = (i < Bsz) ? g_self[i] : g_self[(1 + t) * Bsz + (i - Bsz)];
    float sd = self * TEMP_INV;
    Z -= __expf(sd);
    S -= sd;
    int M = 2 * g_hist[labels[i & (Bsz - 1)] & 255] - 1;
    g_rowloss[g] = logf(Z) - S / (float)M;
}

// ---------------- 4b) deterministic mean ----------------
__global__ void finalize2(float* __restrict__ out) {
    int tid = threadIdx.x;
    double acc = 0.0;
    #pragma unroll
    for (int k = 0; k < 16; ++k) acc += (double)g_rowloss[tid * 16 + k];
    #pragma unroll
    for (int o = 16; o; o >>= 1) acc += __shfl_xor_sync(0xffffffffu, acc, o);
    __shared__ double ws[32];
    if ((tid & 31) == 0) ws[tid >> 5] = acc;
    __syncthreads();
    if (tid == 0) {
        double s = 0.0;
        #pragma unroll
        for (int i = 0; i < 32; ++i) s += ws[i];
        out[0] = (float)(s / (double)(2 * NROW));
    }
}

// ---------------- launch ----------------
extern "C" void kernel_launch(void* const* d_in, const int* in_sizes, int n_in,
                              void* d_out, int out_size) {
    const float* hs     = (const float*)d_in[0];
    const float* ht0    = (const float*)d_in[1];
    const float* ht1    = (const float*)d_in[2];
    const int*   labels = (const int*)d_in[3];
    float*       out    = (float*)d_out;
    (void)in_sizes; (void)n_in; (void)out_size;

    prep_k<<<3 * Bsz, 256>>>(hs, ht0, ht1);
    hist_k<<<1, 256>>>(labels);

    cudaFuncSetAttribute(contrast_gemm,
                         cudaFuncAttributeMaxDynamicSharedMemorySize, SM_TOTAL);
    dim3 grid(NROW / BM, NROW / BN, 2);
    contrast_gemm<<<grid, 256, SM_TOTAL>>>(labels);

    finalize1<<<16, 1024>>>(labels);
    finalize2<<<1, 1024>>>(out);
}

// round 4
// speedup vs baseline: 14.6329x; 1.7231x over previous
#include <cuda_runtime.h>
#include <cuda_bf16.h>
#include <math.h>
#include <stdint.h>

#define Bsz    4096
#define Dh     256
#define NROW   8192
#define TEMP_INV 10.0f
#define BM     128
#define BN     128
#define BK     32
#define NK     8              // 256 / 32
#define T32    32             // 4096 / 128 tiles per quadrant side
#define ROWB   80             // smem row stride bytes (64B data + 16B pad)
#define STAGE_B (2 * BM * ROWB)          // 20480 B
#define SM_STAGES (3 * STAGE_B)          // 61440
#define SM_CLAB   SM_STAGES              // 128 ints
#define SM_ZRED   (SM_CLAB + 512)
#define SM_SRED   (SM_ZRED + 1024)
#define SM_CZ     (SM_SRED + 1024)       // 128 cols x 4 warps
#define SM_CS     (SM_CZ + 2048)
#define SM_TOTAL  (SM_CS + 2048)         // 68096

// ---------------- device scratch ----------------
__device__ __nv_bfloat16 g_hi[3 * Bsz * Dh];
__device__ float g_self[3 * Bsz];
__device__ int   g_hist[256];
__device__ float g_Zss[T32 * Bsz],      g_Sss[T32 * Bsz];       // hs.hs (shared)
__device__ float g_Ztt[2][T32 * Bsz],   g_Stt[2][T32 * Bsz];    // ht.ht
__device__ float g_Zxh[2][T32 * Bsz],   g_Sxh[2][T32 * Bsz];    // cross -> hs rows
__device__ float g_Zxt[2][T32 * Bsz],   g_Sxt[2][T32 * Bsz];    // cross -> ht rows
__device__ float g_rowloss[2 * NROW];

// ---------------- PTX helpers (family-generic) ----------------
__device__ __forceinline__ uint32_t smem_u32(const void* p) {
    uint32_t a;
    asm("{ .reg .u64 t; cvta.to.shared.u64 t, %1; cvt.u32.u64 %0, t; }" : "=r"(a) : "l"(p));
    return a;
}
__device__ __forceinline__ void cp16(uint32_t dst, const void* src) {
    asm volatile("cp.async.cg.shared.global [%0], [%1], 16;" :: "r"(dst), "l"(src));
}
__device__ __forceinline__ void cp_commit() { asm volatile("cp.async.commit_group;"); }
__device__ __forceinline__ void cp_wait1()  { asm volatile("cp.async.wait_group 1;"); }
__device__ __forceinline__ void ldm4(uint32_t& r0, uint32_t& r1, uint32_t& r2,
                                     uint32_t& r3, uint32_t addr) {
    asm volatile("ldmatrix.sync.aligned.m8n8.x4.shared.b16 {%0,%1,%2,%3}, [%4];"
                 : "=r"(r0), "=r"(r1), "=r"(r2), "=r"(r3) : "r"(addr));
}
__device__ __forceinline__ void mma16816(float* c, const uint32_t* a,
                                         uint32_t b0, uint32_t b1) {
    asm volatile("mma.sync.aligned.m16n8k16.row.col.f32.bf16.bf16.f32 "
                 "{%0,%1,%2,%3}, {%4,%5,%6,%7}, {%8,%9}, {%0,%1,%2,%3};"
                 : "+f"(c[0]), "+f"(c[1]), "+f"(c[2]), "+f"(c[3])
                 : "r"(a[0]), "r"(a[1]), "r"(a[2]), "r"(a[3]), "r"(b0), "r"(b1));
}

// ---------------- 1) normalize + bf16 round + consistent self-dot ----------
__global__ void prep_k(const float* __restrict__ hs, const float* __restrict__ t0,
                       const float* __restrict__ t1) {
    int which = blockIdx.x >> 12;
    int row   = blockIdx.x & (Bsz - 1);
    const float* src = (which == 0) ? hs : (which == 1) ? t0 : t1;
    int t = threadIdx.x;
    float x = src[row * Dh + t];
    float v = x * x;
    #pragma unroll
    for (int o = 16; o; o >>= 1) v += __shfl_xor_sync(0xffffffffu, v, o);
    __shared__ float ws[8];
    if ((t & 31) == 0) ws[t >> 5] = v;
    __syncthreads();
    float ss = ws[0] + ws[1] + ws[2] + ws[3] + ws[4] + ws[5] + ws[6] + ws[7];

    float inv = 1.0f / fmaxf(sqrtf(ss), 1e-12f);
    __nv_bfloat16 h = __float2bfloat16(x * inv);
    float hf = __bfloat162float(h);
    g_hi[(which * Bsz + row) * Dh + t] = h;

    float sv = hf * hf;           // diagonal sim exactly as the MMA sees it
    #pragma unroll
    for (int o = 16; o; o >>= 1) sv += __shfl_xor_sync(0xffffffffu, sv, o);
    __syncthreads();
    if ((t & 31) == 0) ws[t >> 5] = sv;
    __syncthreads();
    if (t == 0)
        g_self[which * Bsz + row] =
            ws[0] + ws[1] + ws[2] + ws[3] + ws[4] + ws[5] + ws[6] + ws[7];
}

// ---------------- 2) label histogram ----------------
__global__ void hist_k(const int* __restrict__ labels) {
    __shared__ int h[256];
    int t = threadIdx.x;
    h[t] = 0;
    __syncthreads();
    for (int i = t; i < Bsz; i += 256) atomicAdd(&h[labels[i] & 255], 1);
    __syncthreads();
    g_hist[t] = h[t];
}

// ---------------- 3) deduped bf16 mma GEMM + dual (row+col) epilogue ------
// grid (bj=32, bi=32, type=5). type 0: hs.hs (tri, shared); 1/2: ht.ht (tri);
// 3/4: hs.ht (full). Symmetric types scatter row-sums AND col-sums.
extern __shared__ char smem[];

__global__ void __launch_bounds__(256, 2)
contrast_gemm(const int* __restrict__ labels) {
    const int type = blockIdx.z;
    const int bi = blockIdx.y, bj = blockIdx.x;
    const bool sym = (type < 3);
    if (sym && bi > bj) return;
    const int t = (type == 2 || type == 4) ? 1 : 0;

    const __nv_bfloat16* hsp = g_hi;
    const __nv_bfloat16* htp = g_hi + (1 + t) * Bsz * Dh;
    const __nv_bfloat16* Ap;
    const __nv_bfloat16* Bp;
    float *rowZ, *rowS, *colZ, *colS;
    if (type == 0) {
        Ap = hsp + bi * BM * Dh;  Bp = hsp + bj * BN * Dh;
        rowZ = g_Zss; rowS = g_Sss; colZ = g_Zss; colS = g_Sss;
    } else if (sym) {
        Ap = htp + bi * BM * Dh;  Bp = htp + bj * BN * Dh;
        rowZ = g_Ztt[t]; rowS = g_Stt[t]; colZ = g_Ztt[t]; colS = g_Stt[t];
    } else {
        Ap = hsp + bi * BM * Dh;  Bp = htp + bj * BN * Dh;
        rowZ = g_Zxh[t]; rowS = g_Sxh[t]; colZ = g_Zxt[t]; colS = g_Sxt[t];
    }
    rowZ += bj * Bsz + bi * BM;  rowS += bj * Bsz + bi * BM;
    colZ += bi * Bsz + bj * BN;  colS += bi * Bsz + bj * BN;
    const bool do_col = !(sym && bi == bj);

    const int tid = threadIdx.x;
    const int wid = tid >> 5, lid = tid & 31;
    const uint32_t sb = smem_u32(smem);

    if (tid < BN)
        *reinterpret_cast<int*>(smem + SM_CLAB + tid * 4) = labels[bj * BN + tid];

    const int cr = tid >> 2, cc = tid & 3;
    auto load_tile = [&](int kk, int stage) {
        uint32_t dst = sb + stage * STAGE_B;
        const __nv_bfloat16* ga = Ap + cr * Dh + kk + cc * 8;
        const __nv_bfloat16* gb = Bp + cr * Dh + kk + cc * 8;
        cp16(dst + cr * ROWB + cc * 16,                    ga);
        cp16(dst + (cr + 64) * ROWB + cc * 16,             ga + 64 * Dh);
        cp16(dst + BM * ROWB + cr * ROWB + cc * 16,        gb);
        cp16(dst + BM * ROWB + (cr + 64) * ROWB + cc * 16, gb + 64 * Dh);
    };

    load_tile(0, 0);
    cp_commit();
    load_tile(BK, 1);
    cp_commit();

    const int wr = wid & 3, wc = wid >> 2;
    const int lrow = lid & 15;
    const int koff = (lid & 16) ? 16 : 0;

    float c[2][8][4];
    #pragma unroll
    for (int mi = 0; mi < 2; ++mi)
        #pragma unroll
        for (int ni = 0; ni < 8; ++ni)
            #pragma unroll
            for (int e = 0; e < 4; ++e) c[mi][ni][e] = 0.f;

    for (int k = 0; k < NK; ++k) {
        cp_wait1();
        __syncthreads();
        if (k + 2 < NK) load_tile((k + 2) * BK, (k + 2) % 3);
        cp_commit();

        uint32_t sA = sb + (k % 3) * STAGE_B;
        uint32_t sB = sA + BM * ROWB;

        #pragma unroll
        for (int ks = 0; ks < 2; ++ks) {
            uint32_t a[2][4], b[4][4];
            #pragma unroll
            for (int mi = 0; mi < 2; ++mi)
                ldm4(a[mi][0], a[mi][1], a[mi][2], a[mi][3],
                     sA + (32 * wr + 16 * mi + lrow) * ROWB + ks * 32 + koff);
            #pragma unroll
            for (int nj = 0; nj < 4; ++nj)
                ldm4(b[nj][0], b[nj][1], b[nj][2], b[nj][3],
                     sB + (64 * wc + 16 * nj + lrow) * ROWB + ks * 32 + koff);
            #pragma unroll
            for (int mi = 0; mi < 2; ++mi)
                #pragma unroll
                for (int ni = 0; ni < 8; ++ni) {
                    int nj = ni >> 1, h = ni & 1;
                    mma16816(c[mi][ni], a[mi], b[nj][h], b[nj][2 + h]);
                }
        }
        __syncthreads();
    }

    // ---- epilogue: exp + masked sums, row AND column reductions ----
    const int* clab = reinterpret_cast<const int*>(smem + SM_CLAB);
    float* s_z  = reinterpret_cast<float*>(smem + SM_ZRED);
    float* s_s  = reinterpret_cast<float*>(smem + SM_SRED);
    float* s_cz = reinterpret_cast<float*>(smem + SM_CZ);
    float* s_cs = reinterpret_cast<float*>(smem + SM_CS);

    int rlab[4];
    #pragma unroll
    for (int q = 0; q < 4; ++q)
        rlab[q] = labels[bi * BM + 32 * wr + (lid >> 2) + 8 * q];

    float zk[4], sk[4], czp[16], csp[16];
    #pragma unroll
    for (int q = 0; q < 4; ++q) { zk[q] = 0.f; sk[q] = 0.f; }
    #pragma unroll
    for (int q = 0; q < 16; ++q) { czp[q] = 0.f; csp[q] = 0.f; }

    #pragma unroll
    for (int mi = 0; mi < 2; ++mi)
        #pragma unroll
        for (int ni = 0; ni < 8; ++ni)
            #pragma unroll
            for (int e = 0; e < 4; ++e) {
                int q = mi * 2 + (e >> 1);
                int p = e & 1;
                int col = 64 * wc + 8 * ni + (lid & 3) * 2 + p;
                float lg = c[mi][ni][e] * TEMP_INV;
                float ex = __expf(lg);
                zk[q] += ex;
                czp[ni * 2 + p] += ex;
                if (clab[col] == rlab[q]) { sk[q] += lg; csp[ni * 2 + p] += lg; }
            }

    // row reduce across the 4 column-lanes
    #pragma unroll
    for (int q = 0; q < 4; ++q) {
        #pragma unroll
        for (int o = 1; o < 4; o <<= 1) {
            zk[q] += __shfl_xor_sync(0xffffffffu, zk[q], o);
            sk[q] += __shfl_xor_sync(0xffffffffu, sk[q], o);
        }
    }
    if ((lid & 3) == 0) {
        #pragma unroll
        for (int q = 0; q < 4; ++q) {
            int row = 32 * wr + (lid >> 2) + 8 * q;
            s_z[row * 2 + wc] = zk[q];
            s_s[row * 2 + wc] = sk[q];
        }
    }

    // column reduce across the 8 row-lane-groups
    if (do_col) {
        #pragma unroll
        for (int q = 0; q < 16; ++q) {
            #pragma unroll
            for (int o = 4; o < 32; o <<= 1) {
                czp[q] += __shfl_xor_sync(0xffffffffu, czp[q], o);
                csp[q] += __shfl_xor_sync(0xffffffffu, csp[q], o);
            }
        }
        if (lid < 4) {
            #pragma unroll
            for (int q = 0; q < 16; ++q) {
                int col = 64 * wc + 8 * (q >> 1) + lid * 2 + (q & 1);
                s_cz[col * 4 + wr] = czp[q];
                s_cs[col * 4 + wr] = csp[q];
            }
        }
    }
    __syncthreads();

    if (tid < BM) {
        rowZ[tid] = s_z[tid * 2] + s_z[tid * 2 + 1];
        rowS[tid] = s_s[tid * 2] + s_s[tid * 2 + 1];
        if (do_col) {
            colZ[tid] = s_cz[tid * 4] + s_cz[tid * 4 + 1]
                      + s_cz[tid * 4 + 2] + s_cz[tid * 4 + 3];
            colS[tid] = s_cs[tid * 4] + s_cs[tid * 4 + 1]
                      + s_cs[tid * 4 + 2] + s_cs[tid * 4 + 3];
        }
    }
}

// ---------------- 4a) per-row loss ----------------
__global__ void finalize1(const int* __restrict__ labels) {
    int g = blockIdx.x * 1024 + threadIdx.x;     // 0..16383
    int t = g >> 13;
    int i = g & (NROW - 1);
    float Z = 0.f, S = 0.f, self;
    if (i < Bsz) {
        #pragma unroll
        for (int c = 0; c < T32; ++c) {
            Z += g_Zss[c * Bsz + i] + g_Zxh[t][c * Bsz + i];
            S += g_Sss[c * Bsz + i] + g_Sxh[t][c * Bsz + i];
        }
        self = g_self[i];
    } else {
        int ii = i - Bsz;
        #pragma unroll
        for (int c = 0; c < T32; ++c) {
            Z += g_Ztt[t][c * Bsz + ii] + g_Zxt[t][c * Bsz + ii];
            S += g_Stt[t][c * Bsz + ii] + g_Sxt[t][c * Bsz + ii];
        }
        self = g_self[(1 + t) * Bsz + ii];
    }
    float sd = self * TEMP_INV;
    Z -= __expf(sd);
    S -= sd;
    int M = 2 * g_hist[labels[i & (Bsz - 1)] & 255] - 1;
    g_rowloss[g] = logf(Z) - S / (float)M;
}

// ---------------- 4b) deterministic mean ----------------
__global__ void finalize2(float* __restrict__ out) {
    int tid = threadIdx.x;
    double acc = 0.0;
    #pragma unroll
    for (int k = 0; k < 16; ++k) acc += (double)g_rowloss[tid * 16 + k];
    #pragma unroll
    for (int o = 16; o; o >>= 1) acc += __shfl_xor_sync(0xffffffffu, acc, o);
    __shared__ double ws[32];
    if ((tid & 31) == 0) ws[tid >> 5] = acc;
    __syncthreads();
    if (tid == 0) {
        double s = 0.0;
        #pragma unroll
        for (int i = 0; i < 32; ++i) s += ws[i];
        out[0] = (float)(s / (double)(2 * NROW));
    }
}

// ---------------- launch ----------------
extern "C" void kernel_launch(void* const* d_in, const int* in_sizes, int n_in,
                              void* d_out, int out_size) {
    const float* hs     = (const float*)d_in[0];
    const float* ht0    = (const float*)d_in[1];
    const float* ht1    = (const float*)d_in[2];
    const int*   labels = (const int*)d_in[3];
    float*       out    = (float*)d_out;
    (void)in_sizes; (void)n_in; (void)out_size;

    prep_k<<<3 * Bsz, 256>>>(hs, ht0, ht1);
    hist_k<<<1, 256>>>(labels);

    cudaFuncSetAttribute(contrast_gemm,
                         cudaFuncAttributeMaxDynamicSharedMemorySize, SM_TOTAL);
    dim3 grid(T32, T32, 5);
    contrast_gemm<<<grid, 256, SM_TOTAL>>>(labels);

    finalize1<<<16, 1024>>>(labels);
    finalize2<<<1, 1024>>>(out);
}

// round 5
// speedup vs baseline: 17.0636x; 1.1661x over previous
#include <cuda_runtime.h>
#include <cuda_bf16.h>
#include <math.h>
#include <stdint.h>

#define Bsz    4096
#define Dh     256
#define NROW   8192
#define TEMP_INV 10.0f
#define BM     128
#define BN     128
#define BK     32
#define NK     8              // 256 / 32
#define T32    32             // 4096 / 128 tiles per quadrant side
#define NBLK_SYM   528        // 32*33/2
#define NBLK_TOTAL (3 * NBLK_SYM + 2 * 1024)   // 3632
#define ROWB   80
#define STAGE_B (2 * BM * ROWB)
#define SM_STAGES (3 * STAGE_B)
#define SM_CLAB   SM_STAGES
#define SM_ZRED   (SM_CLAB + 512)
#define SM_SRED   (SM_ZRED + 1024)
#define SM_CZ     (SM_SRED + 1024)
#define SM_CS     (SM_CZ + 2048)
#define SM_TOTAL  (SM_CS + 2048)         // 68096

// ---------------- device scratch ----------------
__device__ __nv_bfloat16 g_hi[3 * Bsz * Dh];
__device__ float g_self[3 * Bsz];
__device__ int   g_hist[256];
__device__ float g_Zss[T32 * Bsz],      g_Sss[T32 * Bsz];
__device__ float g_Ztt[2][T32 * Bsz],   g_Stt[2][T32 * Bsz];
__device__ float g_Zxh[2][T32 * Bsz],   g_Sxh[2][T32 * Bsz];
__device__ float g_Zxt[2][T32 * Bsz],   g_Sxt[2][T32 * Bsz];
__device__ double g_bsum[128];

// ---------------- PTX helpers (family-generic) ----------------
__device__ __forceinline__ uint32_t smem_u32(const void* p) {
    uint32_t a;
    asm("{ .reg .u64 t; cvta.to.shared.u64 t, %1; cvt.u32.u64 %0, t; }" : "=r"(a) : "l"(p));
    return a;
}
__device__ __forceinline__ void cp16(uint32_t dst, const void* src) {
    asm volatile("cp.async.cg.shared.global [%0], [%1], 16;" :: "r"(dst), "l"(src));
}
__device__ __forceinline__ void cp_commit() { asm volatile("cp.async.commit_group;"); }
__device__ __forceinline__ void cp_wait1()  { asm volatile("cp.async.wait_group 1;"); }
__device__ __forceinline__ void ldm4(uint32_t& r0, uint32_t& r1, uint32_t& r2,
                                     uint32_t& r3, uint32_t addr) {
    asm volatile("ldmatrix.sync.aligned.m8n8.x4.shared.b16 {%0,%1,%2,%3}, [%4];"
                 : "=r"(r0), "=r"(r1), "=r"(r2), "=r"(r3) : "r"(addr));
}
__device__ __forceinline__ void mma16816(float* c, const uint32_t* a,
                                         uint32_t b0, uint32_t b1) {
    asm volatile("mma.sync.aligned.m16n8k16.row.col.f32.bf16.bf16.f32 "
                 "{%0,%1,%2,%3}, {%4,%5,%6,%7}, {%8,%9}, {%0,%1,%2,%3};"
                 : "+f"(c[0]), "+f"(c[1]), "+f"(c[2]), "+f"(c[3])
                 : "r"(a[0]), "r"(a[1]), "r"(a[2]), "r"(a[3]), "r"(b0), "r"(b1));
}

// ------- 1) normalize + bf16 round + consistent self-dot (warp per row) ----
__global__ void prep_k(const float* __restrict__ hs, const float* __restrict__ t0,
                       const float* __restrict__ t1) {
    const int w = threadIdx.x >> 5, lane = threadIdx.x & 31;
    const int which = blockIdx.x >> 9;                 // 512 blocks per tensor
    const int row = ((blockIdx.x & 511) << 3) + w;     // 8 rows per block
    const float* src = (which == 0) ? hs : (which == 1) ? t0 : t1;

    const float4* p = reinterpret_cast<const float4*>(src + row * Dh) + lane * 2;
    float4 v0 = p[0], v1 = p[1];
    float x[8] = {v0.x, v0.y, v0.z, v0.w, v1.x, v1.y, v1.z, v1.w};

    float ss = 0.f;
    #pragma unroll
    for (int i = 0; i < 8; ++i) ss += x[i] * x[i];
    #pragma unroll
    for (int o = 16; o; o >>= 1) ss += __shfl_xor_sync(0xffffffffu, ss, o);

    float inv = 1.0f / fmaxf(sqrtf(ss), 1e-12f);

    __nv_bfloat162 h2[4];
    float sv = 0.f;
    #pragma unroll
    for (int i = 0; i < 4; ++i) {
        __nv_bfloat16 a = __float2bfloat16(x[2*i]   * inv);
        __nv_bfloat16 b = __float2bfloat16(x[2*i+1] * inv);
        h2[i] = __nv_bfloat162(a, b);
        float fa = __bfloat162float(a), fb = __bfloat162float(b);
        sv += fa * fa + fb * fb;
    }
    reinterpret_cast<uint4*>(g_hi + (which * Bsz + row) * Dh)[lane] =
        *reinterpret_cast<uint4*>(h2);

    #pragma unroll
    for (int o = 16; o; o >>= 1) sv += __shfl_xor_sync(0xffffffffu, sv, o);
    if (lane == 0) g_self[which * Bsz + row] = sv;
}

// ---------------- 2) label histogram ----------------
__global__ void hist_k(const int* __restrict__ labels) {
    __shared__ int h[256];
    int t = threadIdx.x;
    if (t < 256) h[t] = 0;
    __syncthreads();
    for (int i = t; i < Bsz; i += 1024) atomicAdd(&h[labels[i] & 255], 1);
    __syncthreads();
    if (t < 256) g_hist[t] = h[t];
}

// ---------------- 3) deduped bf16 mma GEMM + dual (row+col) epilogue ------
extern __shared__ char smem[];

__global__ void __launch_bounds__(256, 2)
contrast_gemm(const int* __restrict__ labels) {
    // ---- compact 1D block decode: 3 triangles + 2 full grids ----
    int id = blockIdx.x;
    int type, bi, bj;
    if (id < 3 * NBLK_SYM) {
        type = id / NBLK_SYM;
        int r = id - type * NBLK_SYM;
        int b = 0;
        while (r >= T32 - b) { r -= T32 - b; ++b; }
        bi = b; bj = b + r;
    } else {
        int id2 = id - 3 * NBLK_SYM;
        type = 3 + (id2 >> 10);
        bi = (id2 & 1023) >> 5;
        bj = id2 & 31;
    }
    const bool sym = (type < 3);
    const int t = (type == 2 || type == 4) ? 1 : 0;

    const __nv_bfloat16* hsp = g_hi;
    const __nv_bfloat16* htp = g_hi + (1 + t) * Bsz * Dh;
    const __nv_bfloat16* Ap;
    const __nv_bfloat16* Bp;
    float *rowZ, *rowS, *colZ, *colS;
    if (type == 0) {
        Ap = hsp + bi * BM * Dh;  Bp = hsp + bj * BN * Dh;
        rowZ = g_Zss; rowS = g_Sss; colZ = g_Zss; colS = g_Sss;
    } else if (sym) {
        Ap = htp + bi * BM * Dh;  Bp = htp + bj * BN * Dh;
        rowZ = g_Ztt[t]; rowS = g_Stt[t]; colZ = g_Ztt[t]; colS = g_Stt[t];
    } else {
        Ap = hsp + bi * BM * Dh;  Bp = htp + bj * BN * Dh;
        rowZ = g_Zxh[t]; rowS = g_Sxh[t]; colZ = g_Zxt[t]; colS = g_Sxt[t];
    }
    rowZ += bj * Bsz + bi * BM;  rowS += bj * Bsz + bi * BM;
    colZ += bi * Bsz + bj * BN;  colS += bi * Bsz + bj * BN;
    const bool do_col = !(sym && bi == bj);

    const int tid = threadIdx.x;
    const int wid = tid >> 5, lid = tid & 31;
    const uint32_t sb = smem_u32(smem);

    if (tid < BN)
        *reinterpret_cast<int*>(smem + SM_CLAB + tid * 4) = labels[bj * BN + tid];

    const int cr = tid >> 2, cc = tid & 3;
    auto load_tile = [&](int kk, int stage) {
        uint32_t dst = sb + stage * STAGE_B;
        const __nv_bfloat16* ga = Ap + cr * Dh + kk + cc * 8;
        const __nv_bfloat16* gb = Bp + cr * Dh + kk + cc * 8;
        cp16(dst + cr * ROWB + cc * 16,                    ga);
        cp16(dst + (cr + 64) * ROWB + cc * 16,             ga + 64 * Dh);
        cp16(dst + BM * ROWB + cr * ROWB + cc * 16,        gb);
        cp16(dst + BM * ROWB + (cr + 64) * ROWB + cc * 16, gb + 64 * Dh);
    };

    load_tile(0, 0);
    cp_commit();
    load_tile(BK, 1);
    cp_commit();

    const int wr = wid & 3, wc = wid >> 2;
    const int lrow = lid & 15;
    const int koff = (lid & 16) ? 16 : 0;

    float c[2][8][4];
    #pragma unroll
    for (int mi = 0; mi < 2; ++mi)
        #pragma unroll
        for (int ni = 0; ni < 8; ++ni)
            #pragma unroll
            for (int e = 0; e < 4; ++e) c[mi][ni][e] = 0.f;

    for (int k = 0; k < NK; ++k) {
        cp_wait1();
        __syncthreads();
        if (k + 2 < NK) load_tile((k + 2) * BK, (k + 2) % 3);
        cp_commit();

        uint32_t sA = sb + (k % 3) * STAGE_B;
        uint32_t sB = sA + BM * ROWB;

        #pragma unroll
        for (int ks = 0; ks < 2; ++ks) {
            uint32_t a[2][4], b[4][4];
            #pragma unroll
            for (int mi = 0; mi < 2; ++mi)
                ldm4(a[mi][0], a[mi][1], a[mi][2], a[mi][3],
                     sA + (32 * wr + 16 * mi + lrow) * ROWB + ks * 32 + koff);
            #pragma unroll
            for (int nj = 0; nj < 4; ++nj)
                ldm4(b[nj][0], b[nj][1], b[nj][2], b[nj][3],
                     sB + (64 * wc + 16 * nj + lrow) * ROWB + ks * 32 + koff);
            #pragma unroll
            for (int mi = 0; mi < 2; ++mi)
                #pragma unroll
                for (int ni = 0; ni < 8; ++ni) {
                    int nj = ni >> 1, h = ni & 1;
                    mma16816(c[mi][ni], a[mi], b[nj][h], b[nj][2 + h]);
                }
        }
        __syncthreads();
    }

    // ---- epilogue ----
    const int* clab = reinterpret_cast<const int*>(smem + SM_CLAB);
    float* s_z  = reinterpret_cast<float*>(smem + SM_ZRED);
    float* s_s  = reinterpret_cast<float*>(smem + SM_SRED);
    float* s_cz = reinterpret_cast<float*>(smem + SM_CZ);
    float* s_cs = reinterpret_cast<float*>(smem + SM_CS);

    int rlab[4];
    #pragma unroll
    for (int q = 0; q < 4; ++q)
        rlab[q] = labels[bi * BM + 32 * wr + (lid >> 2) + 8 * q];

    float zk[4], sk[4], czp[16], csp[16];
    #pragma unroll
    for (int q = 0; q < 4; ++q) { zk[q] = 0.f; sk[q] = 0.f; }
    #pragma unroll
    for (int q = 0; q < 16; ++q) { czp[q] = 0.f; csp[q] = 0.f; }

    #pragma unroll
    for (int mi = 0; mi < 2; ++mi)
        #pragma unroll
        for (int ni = 0; ni < 8; ++ni)
            #pragma unroll
            for (int e = 0; e < 4; ++e) {
                int q = mi * 2 + (e >> 1);
                int p = e & 1;
                int col = 64 * wc + 8 * ni + (lid & 3) * 2 + p;
                float lg = c[mi][ni][e] * TEMP_INV;
                float ex = __expf(lg);
                zk[q] += ex;
                czp[ni * 2 + p] += ex;
                if (clab[col] == rlab[q]) { sk[q] += lg; csp[ni * 2 + p] += lg; }
            }

    #pragma unroll
    for (int q = 0; q < 4; ++q) {
        #pragma unroll
        for (int o = 1; o < 4; o <<= 1) {
            zk[q] += __shfl_xor_sync(0xffffffffu, zk[q], o);
            sk[q] += __shfl_xor_sync(0xffffffffu, sk[q], o);
        }
    }
    if ((lid & 3) == 0) {
        #pragma unroll
        for (int q = 0; q < 4; ++q) {
            int row = 32 * wr + (lid >> 2) + 8 * q;
            s_z[row * 2 + wc] = zk[q];
            s_s[row * 2 + wc] = sk[q];
        }
    }

    if (do_col) {
        #pragma unroll
        for (int q = 0; q < 16; ++q) {
            #pragma unroll
            for (int o = 4; o < 32; o <<= 1) {
                czp[q] += __shfl_xor_sync(0xffffffffu, czp[q], o);
                csp[q] += __shfl_xor_sync(0xffffffffu, csp[q], o);
            }
        }
        if (lid < 4) {
            #pragma unroll
            for (int q = 0; q < 16; ++q) {
                int col = 64 * wc + 8 * (q >> 1) + lid * 2 + (q & 1);
                s_cz[col * 4 + wr] = czp[q];
                s_cs[col * 4 + wr] = csp[q];
            }
        }
    }
    __syncthreads();

    if (tid < BM) {
        rowZ[tid] = s_z[tid * 2] + s_z[tid * 2 + 1];
        rowS[tid] = s_s[tid * 2] + s_s[tid * 2 + 1];
        if (do_col) {
            colZ[tid] = s_cz[tid * 4] + s_cz[tid * 4 + 1]
                      + s_cz[tid * 4 + 2] + s_cz[tid * 4 + 3];
            colS[tid] = s_cs[tid * 4] + s_cs[tid * 4 + 1]
                      + s_cs[tid * 4 + 2] + s_cs[tid * 4 + 3];
        }
    }
}

// ------- 4a) per-row loss + per-block double partial (grid 128 x 128) -----
__global__ void finalize1(const int* __restrict__ labels) {
    int g = blockIdx.x * 128 + threadIdx.x;      // 0..16383
    int t = g >> 13;
    int i = g & (NROW - 1);
    float Z = 0.f, S = 0.f, self;
    if (i < Bsz) {
        #pragma unroll
        for (int c = 0; c < T32; ++c) {
            Z += g_Zss[c * Bsz + i] + g_Zxh[t][c * Bsz + i];
            S += g_Sss[c * Bsz + i] + g_Sxh[t][c * Bsz + i];
        }
        self = g_self[i];
    } else {
        int ii = i - Bsz;
        #pragma unroll
        for (int c = 0; c < T32; ++c) {
            Z += g_Ztt[t][c * Bsz + ii] + g_Zxt[t][c * Bsz + ii];
            S += g_Stt[t][c * Bsz + ii] + g_Sxt[t][c * Bsz + ii];
        }
        self = g_self[(1 + t) * Bsz + ii];
    }
    float sd = self * TEMP_INV;
    Z -= __expf(sd);
    S -= sd;
    int M = 2 * g_hist[labels[i & (Bsz - 1)] & 255] - 1;
    double acc = (double)(logf(Z) - S / (float)M);

    #pragma unroll
    for (int o = 16; o; o >>= 1) acc += __shfl_xor_sync(0xffffffffu, acc, o);
    __shared__ double ws[4];
    int lid = threadIdx.x & 31, wid = threadIdx.x >> 5;
    if (lid == 0) ws[wid] = acc;
    __syncthreads();
    if (threadIdx.x == 0)
        g_bsum[blockIdx.x] = ws[0] + ws[1] + ws[2] + ws[3];
}

// ---------------- 4b) deterministic mean of 128 partials ----------------
__global__ void finalize2(float* __restrict__ out) {
    int tid = threadIdx.x;                        // 128 threads
    double acc = g_bsum[tid];
    #pragma unroll
    for (int o = 16; o; o >>= 1) acc += __shfl_xor_sync(0xffffffffu, acc, o);
    __shared__ double ws[4];
    if ((tid & 31) == 0) ws[tid >> 5] = acc;
    __syncthreads();
    if (tid == 0)
        out[0] = (float)((ws[0] + ws[1] + ws[2] + ws[3]) / (double)(2 * NROW));
}

// ---------------- launch ----------------
extern "C" void kernel_launch(void* const* d_in, const int* in_sizes, int n_in,
                              void* d_out, int out_size) {
    const float* hs     = (const float*)d_in[0];
    const float* ht0    = (const float*)d_in[1];
    const float* ht1    = (const float*)d_in[2];
    const int*   labels = (const int*)d_in[3];
    float*       out    = (float*)d_out;
    (void)in_sizes; (void)n_in; (void)out_size;

    prep_k<<<3 * 512, 256>>>(hs, ht0, ht1);
    hist_k<<<1, 1024>>>(labels);

    cudaFuncSetAttribute(contrast_gemm,
                         cudaFuncAttributeMaxDynamicSharedMemorySize, SM_TOTAL);
    contrast_gemm<<<NBLK_TOTAL, 256, SM_TOTAL>>>(labels);

    finalize1<<<128, 128>>>(labels);
    finalize2<<<1, 128>>>(out);
}

// round 6
// speedup vs baseline: 17.3286x; 1.0155x over previous
#include <cuda_runtime.h>
#include <cuda_bf16.h>
#include <math.h>
#include <stdint.h>

#define Bsz    4096
#define Dh     256
#define NROW   8192
#define TEMP_INV 10.0f
#define BM     128
#define BN     128
#define BK     32
#define NK     8
#define T32    32
#define NBLK_SYM   528
#define NBLK_TOTAL (3 * NBLK_SYM + 2 * 1024)   // 3632
#define ROWB   80
#define STAGE_B (2 * BM * ROWB)
#define SM_STAGES (3 * STAGE_B)
#define SM_CLAB   SM_STAGES
#define SM_ZRED   (SM_CLAB + 512)
#define SM_SRED   (SM_ZRED + 1024)
#define SM_CZ     (SM_SRED + 1024)
#define SM_CS     (SM_CZ + 2048)
#define SM_TOTAL  (SM_CS + 2048)         // 68096

// ---------------- device scratch ----------------
__device__ __nv_bfloat16 g_hi[3 * Bsz * Dh];
__device__ float g_self[3 * Bsz];
__device__ int   g_hist[256];
__device__ float g_Zss[T32 * Bsz],      g_Sss[T32 * Bsz];
__device__ float g_Ztt[2][T32 * Bsz],   g_Stt[2][T32 * Bsz];
__device__ float g_Zxh[2][T32 * Bsz],   g_Sxh[2][T32 * Bsz];
__device__ float g_Zxt[2][T32 * Bsz],   g_Sxt[2][T32 * Bsz];
__device__ float g_Zoct[8][2 * NROW],   g_Soct[8][2 * NROW];
__device__ double g_bsum[64];

// ---------------- PTX helpers (family-generic) ----------------
__device__ __forceinline__ uint32_t smem_u32(const void* p) {
    uint32_t a;
    asm("{ .reg .u64 t; cvta.to.shared.u64 t, %1; cvt.u32.u64 %0, t; }" : "=r"(a) : "l"(p));
    return a;
}
__device__ __forceinline__ void cp16(uint32_t dst, const void* src) {
    asm volatile("cp.async.cg.shared.global [%0], [%1], 16;" :: "r"(dst), "l"(src));
}
__device__ __forceinline__ void cp_commit() { asm volatile("cp.async.commit_group;"); }
__device__ __forceinline__ void cp_wait1()  { asm volatile("cp.async.wait_group 1;"); }
__device__ __forceinline__ void ldm4(uint32_t& r0, uint32_t& r1, uint32_t& r2,
                                     uint32_t& r3, uint32_t addr) {
    asm volatile("ldmatrix.sync.aligned.m8n8.x4.shared.b16 {%0,%1,%2,%3}, [%4];"
                 : "=r"(r0), "=r"(r1), "=r"(r2), "=r"(r3) : "r"(addr));
}
__device__ __forceinline__ void mma16816(float* c, const uint32_t* a,
                                         uint32_t b0, uint32_t b1) {
    asm volatile("mma.sync.aligned.m16n8k16.row.col.f32.bf16.bf16.f32 "
                 "{%0,%1,%2,%3}, {%4,%5,%6,%7}, {%8,%9}, {%0,%1,%2,%3};"
                 : "+f"(c[0]), "+f"(c[1]), "+f"(c[2]), "+f"(c[3])
                 : "r"(a[0]), "r"(a[1]), "r"(a[2]), "r"(a[3]), "r"(b0), "r"(b1));
}

// --- 1) normalize + bf16 round + self-dot (warp/row); last block: hist ----
__global__ void prep_k(const float* __restrict__ hs, const float* __restrict__ t0,
                       const float* __restrict__ t1, const int* __restrict__ labels) {
    if (blockIdx.x == 1536) {            // fused label histogram
        __shared__ int h[256];
        int t = threadIdx.x;
        h[t] = 0;
        __syncthreads();
        for (int i = t; i < Bsz; i += 256) atomicAdd(&h[labels[i] & 255], 1);
        __syncthreads();
        g_hist[t] = h[t];
        return;
    }
    const int w = threadIdx.x >> 5, lane = threadIdx.x & 31;
    const int which = blockIdx.x >> 9;
    const int row = ((blockIdx.x & 511) << 3) + w;
    const float* src = (which == 0) ? hs : (which == 1) ? t0 : t1;

    const float4* p = reinterpret_cast<const float4*>(src + row * Dh) + lane * 2;
    float4 v0 = p[0], v1 = p[1];
    float x[8] = {v0.x, v0.y, v0.z, v0.w, v1.x, v1.y, v1.z, v1.w};

    float ss = 0.f;
    #pragma unroll
    for (int i = 0; i < 8; ++i) ss += x[i] * x[i];
    #pragma unroll
    for (int o = 16; o; o >>= 1) ss += __shfl_xor_sync(0xffffffffu, ss, o);

    float inv = 1.0f / fmaxf(sqrtf(ss), 1e-12f);

    __nv_bfloat162 h2[4];
    float sv = 0.f;
    #pragma unroll
    for (int i = 0; i < 4; ++i) {
        __nv_bfloat16 a = __float2bfloat16(x[2*i]   * inv);
        __nv_bfloat16 b = __float2bfloat16(x[2*i+1] * inv);
        h2[i] = __nv_bfloat162(a, b);
        float fa = __bfloat162float(a), fb = __bfloat162float(b);
        sv += fa * fa + fb * fb;
    }
    reinterpret_cast<uint4*>(g_hi + (which * Bsz + row) * Dh)[lane] =
        *reinterpret_cast<uint4*>(h2);

    #pragma unroll
    for (int o = 16; o; o >>= 1) sv += __shfl_xor_sync(0xffffffffu, sv, o);
    if (lane == 0) g_self[which * Bsz + row] = sv;
}

// ---------------- 3) deduped bf16 mma GEMM + dual epilogue ----------------
extern __shared__ char smem[];

__global__ void __launch_bounds__(256, 2)
contrast_gemm(const int* __restrict__ labels) {
    int id = blockIdx.x;
    int type, bi, bj;
    if (id < 3 * NBLK_SYM) {
        type = id / NBLK_SYM;
        int r = id - type * NBLK_SYM;
        int b = 0;
        while (r >= T32 - b) { r -= T32 - b; ++b; }
        bi = b; bj = b + r;
    } else {
        int id2 = id - 3 * NBLK_SYM;
        type = 3 + (id2 >> 10);
        bi = (id2 & 1023) >> 5;
        bj = id2 & 31;
    }
    const bool sym = (type < 3);
    const int t = (type == 2 || type == 4) ? 1 : 0;

    const __nv_bfloat16* hsp = g_hi;
    const __nv_bfloat16* htp = g_hi + (1 + t) * Bsz * Dh;
    const __nv_bfloat16* Ap;
    const __nv_bfloat16* Bp;
    float *rowZ, *rowS, *colZ, *colS;
    if (type == 0) {
        Ap = hsp + bi * BM * Dh;  Bp = hsp + bj * BN * Dh;
        rowZ = g_Zss; rowS = g_Sss; colZ = g_Zss; colS = g_Sss;
    } else if (sym) {
        Ap = htp + bi * BM * Dh;  Bp = htp + bj * BN * Dh;
        rowZ = g_Ztt[t]; rowS = g_Stt[t]; colZ = g_Ztt[t]; colS = g_Stt[t];
    } else {
        Ap = hsp + bi * BM * Dh;  Bp = htp + bj * BN * Dh;
        rowZ = g_Zxh[t]; rowS = g_Sxh[t]; colZ = g_Zxt[t]; colS = g_Sxt[t];
    }
    rowZ += bj * Bsz + bi * BM;  rowS += bj * Bsz + bi * BM;
    colZ += bi * Bsz + bj * BN;  colS += bi * Bsz + bj * BN;
    const bool do_col = !(sym && bi == bj);

    const int tid = threadIdx.x;
    const int wid = tid >> 5, lid = tid & 31;
    const uint32_t sb = smem_u32(smem);

    if (tid < BN)
        *reinterpret_cast<int*>(smem + SM_CLAB + tid * 4) = labels[bj * BN + tid];

    const int cr = tid >> 2, cc = tid & 3;
    auto load_tile = [&](int kk, int stage) {
        uint32_t dst = sb + stage * STAGE_B;
        const __nv_bfloat16* ga = Ap + cr * Dh + kk + cc * 8;
        const __nv_bfloat16* gb = Bp + cr * Dh + kk + cc * 8;
        cp16(dst + cr * ROWB + cc * 16,                    ga);
        cp16(dst + (cr + 64) * ROWB + cc * 16,             ga + 64 * Dh);
        cp16(dst + BM * ROWB + cr * ROWB + cc * 16,        gb);
        cp16(dst + BM * ROWB + (cr + 64) * ROWB + cc * 16, gb + 64 * Dh);
    };

    load_tile(0, 0);
    cp_commit();
    load_tile(BK, 1);
    cp_commit();

    const int wr = wid & 3, wc = wid >> 2;
    const int lrow = lid & 15;
    const int koff = (lid & 16) ? 16 : 0;

    float c[2][8][4];
    #pragma unroll
    for (int mi = 0; mi < 2; ++mi)
        #pragma unroll
        for (int ni = 0; ni < 8; ++ni)
            #pragma unroll
            for (int e = 0; e < 4; ++e) c[mi][ni][e] = 0.f;

    for (int k = 0; k < NK; ++k) {
        cp_wait1();
        __syncthreads();
        if (k + 2 < NK) load_tile((k + 2) * BK, (k + 2) % 3);
        cp_commit();

        uint32_t sA = sb + (k % 3) * STAGE_B;
        uint32_t sB = sA + BM * ROWB;

        #pragma unroll
        for (int ks = 0; ks < 2; ++ks) {
            uint32_t a[2][4], b[4][4];
            #pragma unroll
            for (int mi = 0; mi < 2; ++mi)
                ldm4(a[mi][0], a[mi][1], a[mi][2], a[mi][3],
                     sA + (32 * wr + 16 * mi + lrow) * ROWB + ks * 32 + koff);
            #pragma unroll
            for (int nj = 0; nj < 4; ++nj)
                ldm4(b[nj][0], b[nj][1], b[nj][2], b[nj][3],
                     sB + (64 * wc + 16 * nj + lrow) * ROWB + ks * 32 + koff);
            #pragma unroll
            for (int mi = 0; mi < 2; ++mi)
                #pragma unroll
                for (int ni = 0; ni < 8; ++ni) {
                    int nj = ni >> 1, h = ni & 1;
                    mma16816(c[mi][ni], a[mi], b[nj][h], b[nj][2 + h]);
                }
        }
        __syncthreads();
    }

    // ---- epilogue ----
    const int* clab = reinterpret_cast<const int*>(smem + SM_CLAB);
    float* s_z  = reinterpret_cast<float*>(smem + SM_ZRED);
    float* s_s  = reinterpret_cast<float*>(smem + SM_SRED);
    float* s_cz = reinterpret_cast<float*>(smem + SM_CZ);
    float* s_cs = reinterpret_cast<float*>(smem + SM_CS);

    int rlab[4];
    #pragma unroll
    for (int q = 0; q < 4; ++q)
        rlab[q] = labels[bi * BM + 32 * wr + (lid >> 2) + 8 * q];

    float zk[4], sk[4], czp[16], csp[16];
    #pragma unroll
    for (int q = 0; q < 4; ++q) { zk[q] = 0.f; sk[q] = 0.f; }
    #pragma unroll
    for (int q = 0; q < 16; ++q) { czp[q] = 0.f; csp[q] = 0.f; }

    #pragma unroll
    for (int mi = 0; mi < 2; ++mi)
        #pragma unroll
        for (int ni = 0; ni < 8; ++ni)
            #pragma unroll
            for (int e = 0; e < 4; ++e) {
                int q = mi * 2 + (e >> 1);
                int p = e & 1;
                int col = 64 * wc + 8 * ni + (lid & 3) * 2 + p;
                float lg = c[mi][ni][e] * TEMP_INV;
                float ex = __expf(lg);
                zk[q] += ex;
                czp[ni * 2 + p] += ex;
                if (clab[col] == rlab[q]) { sk[q] += lg; csp[ni * 2 + p] += lg; }
            }

    #pragma unroll
    for (int q = 0; q < 4; ++q) {
        #pragma unroll
        for (int o = 1; o < 4; o <<= 1) {
            zk[q] += __shfl_xor_sync(0xffffffffu, zk[q], o);
            sk[q] += __shfl_xor_sync(0xffffffffu, sk[q], o);
        }
    }
    if ((lid & 3) == 0) {
        #pragma unroll
        for (int q = 0; q < 4; ++q) {
            int row = 32 * wr + (lid >> 2) + 8 * q;
            s_z[row * 2 + wc] = zk[q];
            s_s[row * 2 + wc] = sk[q];
        }
    }

    if (do_col) {
        #pragma unroll
        for (int q = 0; q < 16; ++q) {
            #pragma unroll
            for (int o = 4; o < 32; o <<= 1) {
                czp[q] += __shfl_xor_sync(0xffffffffu, czp[q], o);
                csp[q] += __shfl_xor_sync(0xffffffffu, csp[q], o);
            }
        }
        if (lid < 4) {
            #pragma unroll
            for (int q = 0; q < 16; ++q) {
                int col = 64 * wc + 8 * (q >> 1) + lid * 2 + (q & 1);
                s_cz[col * 4 + wr] = czp[q];
                s_cs[col * 4 + wr] = csp[q];
            }
        }
    }
    __syncthreads();

    if (tid < BM) {
        rowZ[tid] = s_z[tid * 2] + s_z[tid * 2 + 1];
        rowS[tid] = s_s[tid * 2] + s_s[tid * 2 + 1];
        if (do_col) {
            colZ[tid] = s_cz[tid * 4] + s_cz[tid * 4 + 1]
                      + s_cz[tid * 4 + 2] + s_cz[tid * 4 + 3];
            colS[tid] = s_cs[tid * 4] + s_cs[tid * 4 + 1]
                      + s_cs[tid * 4 + 2] + s_cs[tid * 4 + 3];
        }
    }
}

// ------- 4a) octant partial sums: grid (64, 8) x 256 threads --------------
__global__ void finalize1a() {
    int g = blockIdx.x * 256 + threadIdx.x;      // 0..16383
    int oct = blockIdx.y;                        // 0..7
    int t = g >> 13;
    int i = g & (NROW - 1);
    float Z = 0.f, S = 0.f;
    if (i < Bsz) {
        #pragma unroll
        for (int c = oct * 4; c < oct * 4 + 4; ++c) {
            Z += g_Zss[c * Bsz + i] + g_Zxh[t][c * Bsz + i];
            S += g_Sss[c * Bsz + i] + g_Sxh[t][c * Bsz + i];
        }
    } else {
        int ii = i - Bsz;
        #pragma unroll
        for (int c = oct * 4; c < oct * 4 + 4; ++c) {
            Z += g_Ztt[t][c * Bsz + ii] + g_Zxt[t][c * Bsz + ii];
            S += g_Stt[t][c * Bsz + ii] + g_Sxt[t][c * Bsz + ii];
        }
    }
    g_Zoct[oct][g] = Z;
    g_Soct[oct][g] = S;
}

// ------- 4b) per-row loss + per-block double partial (grid 64 x 256) ------
__global__ void finalize1b(const int* __restrict__ labels) {
    int g = blockIdx.x * 256 + threadIdx.x;
    int t = g >> 13;
    int i = g & (NROW - 1);
    float Z = 0.f, S = 0.f;
    #pragma unroll
    for (int o = 0; o < 8; ++o) { Z += g_Zoct[o][g]; S += g_Soct[o][g]; }
    float self = (i < Bsz) ? g_self[i] : g_self[(1 + t) * Bsz + (i - Bsz)];
    float sd = self * TEMP_INV;
    Z -= __expf(sd);
    S -= sd;
    int M = 2 * g_hist[labels[i & (Bsz - 1)] & 255] - 1;
    double acc = (double)(logf(Z) - S / (float)M);

    #pragma unroll
    for (int o = 16; o; o >>= 1) acc += __shfl_xor_sync(0xffffffffu, acc, o);
    __shared__ double ws[8];
    int lid = threadIdx.x & 31, wid = threadIdx.x >> 5;
    if (lid == 0) ws[wid] = acc;
    __syncthreads();
    if (threadIdx.x == 0) {
        double s = 0.0;
        #pragma unroll
        for (int k = 0; k < 8; ++k) s += ws[k];
        g_bsum[blockIdx.x] = s;
    }
}

// ---------------- 4c) deterministic mean of 64 partials ----------------
__global__ void finalize2(float* __restrict__ out) {
    int tid = threadIdx.x;                        // 64 threads
    double acc = g_bsum[tid];
    #pragma unroll
    for (int o = 16; o; o >>= 1) acc += __shfl_xor_sync(0xffffffffu, acc, o);
    __shared__ double ws[2];
    if ((tid & 31) == 0) ws[tid >> 5] = acc;
    __syncthreads();
    if (tid == 0)
        out[0] = (float)((ws[0] + ws[1]) / (double)(2 * NROW));
}

// ---------------- launch ----------------
extern "C" void kernel_launch(void* const* d_in, const int* in_sizes, int n_in,
                              void* d_out, int out_size) {
    const float* hs     = (const float*)d_in[0];
    const float* ht0    = (const float*)d_in[1];
    const float* ht1    = (const float*)d_in[2];
    const int*   labels = (const int*)d_in[3];
    float*       out    = (float*)d_out;
    (void)in_sizes; (void)n_in; (void)out_size;

    prep_k<<<3 * 512 + 1, 256>>>(hs, ht0, ht1, labels);

    cudaFuncSetAttribute(contrast_gemm,
                         cudaFuncAttributeMaxDynamicSharedMemorySize, SM_TOTAL);
    contrast_gemm<<<NBLK_TOTAL, 256, SM_TOTAL>>>(labels);

    finalize1a<<<dim3(64, 8), 256>>>();
    finalize1b<<<64, 256>>>(labels);
    finalize2<<<1, 64>>>(out);
}